// round 5
// baseline (speedup 1.0000x reference)
#include <cuda_runtime.h>
#include <cuda_fp16.h>
#include <cstdint>

// ============================ constants ============================

static constexpr int B_ROWS = 65536;   // query rows
static constexpr int D_DIM  = 512;     // feature dim
static constexpr int C_DIM  = 1024;    // memory slots

static constexpr int MT = 256;         // CTA tile M
static constexpr int NT = 128;         // CTA tile N
static constexpr int KC = 64;          // K per smem stage (64 halves = 128B rows)

static constexpr uint32_t A_STAGE = MT * 128;             // 32768
static constexpr uint32_t B_STAGE = NT * 128;             // 16384
static constexpr uint32_t STAGE_BYTES = A_STAGE + B_STAGE; // 49152
static constexpr uint32_t SMEM_TOTAL  = 3 * STAGE_BYTES;   // 147456

// ============================ device scratch ============================

__device__ __align__(1024) __half g_qn[(size_t)B_ROWS * D_DIM];     // 64 MB
__device__ __align__(1024) __half g_kn[(size_t)C_DIM * D_DIM];      // 1 MB
__device__ __align__(1024) __half g_valT[(size_t)C_DIM * C_DIM];    // 2 MB
__device__ __align__(1024) __half g_sharp[(size_t)B_ROWS * C_DIM];  // 128 MB
__device__ float g_rowinv[B_ROWS];

// ============================ helpers ============================

__device__ __forceinline__ uint32_t smem_to_u32(const void* smem_ptr) {
    uint32_t addr;
    asm("{ .reg .u64 tmp; cvta.to.shared.u64 tmp, %1; cvt.u32.u64 %0, tmp; }"
        : "=r"(addr) : "l"(smem_ptr));
    return addr;
}

__device__ __forceinline__ void cp_async16(uint32_t dst, const void* src) {
    asm volatile("cp.async.cg.shared.global [%0], [%1], 16;"
                 :: "r"(dst), "l"(src) : "memory");
}

__device__ __forceinline__ void ldmatrix_x4(uint32_t* r, uint32_t addr) {
    asm volatile("ldmatrix.sync.aligned.m8n8.x4.shared.b16 {%0,%1,%2,%3}, [%4];"
                 : "=r"(r[0]), "=r"(r[1]), "=r"(r[2]), "=r"(r[3]) : "r"(addr));
}

__device__ __forceinline__ void mma16816(float* c, const uint32_t* a,
                                         uint32_t b0, uint32_t b1) {
    asm volatile(
        "mma.sync.aligned.m16n8k16.row.col.f32.f16.f16.f32 "
        "{%0,%1,%2,%3}, {%4,%5,%6,%7}, {%8,%9}, {%0,%1,%2,%3};"
        : "+f"(c[0]), "+f"(c[1]), "+f"(c[2]), "+f"(c[3])
        : "r"(a[0]), "r"(a[1]), "r"(a[2]), "r"(a[3]), "r"(b0), "r"(b1));
}

__device__ __forceinline__ float softabs_f(float x) {
    const float t = 10.f * x;
    const float a = 1.f / (1.f + __expf(5.f - t));
    const float b = 1.f / (1.f + __expf(5.f + t));
    return a + b;
}

// swizzled smem byte offset (used only in cp.async dst precompute)
__device__ __forceinline__ uint32_t swz_off(int row, int kchunk) {
    return (uint32_t)(row * 128 + ((kchunk ^ (row & 7)) << 4));
}

// ============================ prep kernels ============================

__global__ void __launch_bounds__(256) prep_norm_kernel(
    const float* __restrict__ src, __half* __restrict__ dst)
{
    const int wid  = threadIdx.x >> 5;
    const int lane = threadIdx.x & 31;
    const size_t row = (size_t)blockIdx.x * 8 + wid;

    const float4* s4 = (const float4*)(src + row * D_DIM);
    float4 v[4];
    float ss = 0.f;
#pragma unroll
    for (int i = 0; i < 4; i++) {
        v[i] = s4[lane + 32 * i];
        ss += v[i].x * v[i].x + v[i].y * v[i].y + v[i].z * v[i].z + v[i].w * v[i].w;
    }
#pragma unroll
    for (int o = 16; o > 0; o >>= 1) ss += __shfl_xor_sync(0xffffffffu, ss, o);
    const float inv = rsqrtf(ss + 1e-12f);

    uint2* d2 = (uint2*)(dst + row * D_DIM);
#pragma unroll
    for (int i = 0; i < 4; i++) {
        __half2 a = __floats2half2_rn(v[i].x * inv, v[i].y * inv);
        __half2 b = __floats2half2_rn(v[i].z * inv, v[i].w * inv);
        d2[lane + 32 * i] = make_uint2(*reinterpret_cast<uint32_t*>(&a),
                                       *reinterpret_cast<uint32_t*>(&b));
    }
}

__global__ void __launch_bounds__(256) transpose_val_kernel(const float* __restrict__ v)
{
    __shared__ float t[32][33];
    const int tx = threadIdx.x & 31;
    const int ty = threadIdx.x >> 5;
    const int x  = blockIdx.x * 32 + tx;
    const int y0 = blockIdx.y * 32 + ty;
#pragma unroll
    for (int i = 0; i < 4; i++)
        t[ty + i * 8][tx] = v[(size_t)(y0 + i * 8) * C_DIM + x];
    __syncthreads();
    const int x2 = blockIdx.y * 32 + tx;
    const int y2 = blockIdx.x * 32 + ty;
#pragma unroll
    for (int i = 0; i < 4; i++)
        g_valT[(size_t)(y2 + i * 8) * C_DIM + x2] = __float2half(t[tx][ty + i * 8]);
}

// Deterministic per-row sum of g_sharp -> g_rowinv = 1/sum. One warp per row.
__global__ void __launch_bounds__(256) rowsum_kernel()
{
    const int wid  = threadIdx.x >> 5;
    const int lane = threadIdx.x & 31;
    const size_t row = (size_t)blockIdx.x * 8 + wid;

    const uint4* s4 = (const uint4*)(g_sharp + row * C_DIM);
    float ss = 0.f;
#pragma unroll
    for (int i = 0; i < 4; i++) {
        uint4 v = s4[lane + 32 * i];
        const __half2* h2 = (const __half2*)&v;
#pragma unroll
        for (int q = 0; q < 4; q++) {
            float2 f = __half22float2(h2[q]);
            ss += f.x + f.y;
        }
    }
#pragma unroll
    for (int o = 16; o > 0; o >>= 1) ss += __shfl_xor_sync(0xffffffffu, ss, o);
    if (lane == 0) g_rowinv[row] = 1.0f / ss;
}

// ============================ GEMM ============================
// D[m][n] = sum_k A[m][k]*B[n][k]; fp16 in, fp32 accum (mma.sync m16n8k16).
// CTA tile 256x128, 8 warps (4x2), warp tile 64x64, 3-stage cp.async pipeline.
// EPI==0: store softabs(acc) -> g_sharp (fp16)
// EPI==1: store acc * g_rowinv[row] -> out (fp32)
template<int KTOT, int EPI>
__global__ void __launch_bounds__(256, 1)
gemm_kernel(const __half* __restrict__ A, const __half* __restrict__ B,
            float* __restrict__ out)
{
    extern __shared__ char smem[];
    const uint32_t sbase = smem_to_u32(smem);
    const int tid  = threadIdx.x;
    const int lane = tid & 31;
    const int wid  = tid >> 5;
    const int warp_m = wid >> 1;      // 0..3  (64 rows each)
    const int warp_n = wid & 1;       // 0..1  (64 cols each)
    const int mbase = blockIdx.y * MT;
    const int nbase = blockIdx.x * NT;

    constexpr int NCH = KTOT / KC;

    float acc[4][8][4];
#pragma unroll
    for (int a = 0; a < 4; a++)
#pragma unroll
        for (int b = 0; b < 8; b++)
#pragma unroll
            for (int c = 0; c < 4; c++) acc[a][b][c] = 0.f;

    // ---- precomputed ldmatrix addresses (stage-0) ----
    const int lrow15 = lane & 15;
    const int c0  = lane >> 4;             // base 16B-chunk (0/1)
    const int r7  = lrow15 & 7;
    const uint32_t basechunk = (uint32_t)((c0 ^ (r7 & 1)) << 4);
    const uint32_t r6s = (uint32_t)((r7 & 6) << 4);

    uint32_t aAddr0[4], bAddr0[4];
#pragma unroll
    for (int mt = 0; mt < 4; mt++) {
        const int row = warp_m * 64 + mt * 16 + lrow15;
        aAddr0[mt] = sbase + (uint32_t)(row << 7) + basechunk;
    }
#pragma unroll
    for (int p = 0; p < 4; p++) {
        const int row = warp_n * 64 + p * 16 + lrow15;
        bAddr0[p] = sbase + A_STAGE + (uint32_t)(row << 7) + basechunk;
    }

    // ---- precomputed cp.async src/dst bases ----
    const int rA0 = tid >> 3;              // A rows: rA0 + 32*i   (i=0..7)
    const int rB0 = tid >> 3;              // B rows: rB0 + 32*i   (i=0..3)
    const int cch = tid & 7;               // 16B chunk column
    const char* srcA0 = (const char*)(A + (size_t)(mbase + rA0) * KTOT) + cch * 16;
    const char* srcB0 = (const char*)(B + (size_t)(nbase + rB0) * KTOT) + cch * 16;
    const uint32_t dstA0 = sbase + swz_off(rA0, cch);
    const uint32_t dstB0 = sbase + A_STAGE + swz_off(rB0, cch);
    constexpr size_t rowStride = (size_t)32 * KTOT * 2;   // 32 rows in bytes

    auto load_stage = [&](int kc, int s) {
        const uint32_t so = (uint32_t)s * STAGE_BYTES;
        const size_t ko = (size_t)kc * 128;
#pragma unroll
        for (int i = 0; i < 8; i++)
            cp_async16(dstA0 + so + i * 4096u, srcA0 + ko + i * rowStride);
#pragma unroll
        for (int i = 0; i < 4; i++)
            cp_async16(dstB0 + so + i * 4096u, srcB0 + ko + i * rowStride);
        asm volatile("cp.async.commit_group;" ::: "memory");
    };

    auto mma_stage = [&](int s) {
        const uint32_t so = (uint32_t)s * STAGE_BYTES;
#pragma unroll
        for (int ks = 0; ks < 4; ks++) {
            const uint32_t kd = so + (((uint32_t)(ks * 2) << 4) ^ r6s);
            uint32_t bf[4][4];
#pragma unroll
            for (int p = 0; p < 4; p++)
                ldmatrix_x4(bf[p], bAddr0[p] + kd);
#pragma unroll
            for (int mt = 0; mt < 4; mt++) {
                uint32_t af[4];
                ldmatrix_x4(af, aAddr0[mt] + kd);
#pragma unroll
                for (int nt = 0; nt < 8; nt++) {
                    const int p = nt >> 1, lo = nt & 1;
                    mma16816(acc[mt][nt], af, bf[p][lo], bf[p][2 + lo]);
                }
            }
        }
    };

    // ---- 3-stage pipelined main loop, one barrier per K-chunk ----
    load_stage(0, 0);
    load_stage(1, 1);
#pragma unroll 1
    for (int kc = 0; kc < NCH; kc++) {
        if (kc < NCH - 1) asm volatile("cp.async.wait_group 1;" ::: "memory");
        else              asm volatile("cp.async.wait_group 0;" ::: "memory");
        __syncthreads();
        if (kc + 2 < NCH) {
            int s2 = kc + 2;
            load_stage(s2, s2 - (s2 / 3) * 3);
        }
        mma_stage(kc - (kc / 3) * 3);
    }

    // ---- epilogue (registers + global only) ----
    const int g   = lane >> 2;     // 0..7
    const int tig = lane & 3;      // 0..3
#pragma unroll
    for (int mt = 0; mt < 4; mt++) {
        const int rg = mbase + warp_m * 64 + mt * 16 + g;
        if (EPI == 0) {
#pragma unroll
            for (int nt = 0; nt < 8; nt++) {
                const int n = nbase + warp_n * 64 + nt * 8 + tig * 2;
                __half2 h0 = __floats2half2_rn(softabs_f(acc[mt][nt][0]),
                                               softabs_f(acc[mt][nt][1]));
                __half2 h1 = __floats2half2_rn(softabs_f(acc[mt][nt][2]),
                                               softabs_f(acc[mt][nt][3]));
                *(__half2*)(g_sharp + (size_t)rg * C_DIM + n) = h0;
                *(__half2*)(g_sharp + (size_t)(rg + 8) * C_DIM + n) = h1;
            }
        } else {
            const float i0 = g_rowinv[rg];
            const float i1 = g_rowinv[rg + 8];
#pragma unroll
            for (int nt = 0; nt < 8; nt++) {
                const int n = nbase + warp_n * 64 + nt * 8 + tig * 2;
                *(float2*)(out + (size_t)rg * C_DIM + n) =
                    make_float2(acc[mt][nt][0] * i0, acc[mt][nt][1] * i0);
                *(float2*)(out + (size_t)(rg + 8) * C_DIM + n) =
                    make_float2(acc[mt][nt][2] * i1, acc[mt][nt][3] * i1);
            }
        }
    }
}

// ============================ launcher ============================

extern "C" void kernel_launch(void* const* d_in, const int* in_sizes, int n_in,
                              void* d_out, int out_size)
{
    const float* q  = (const float*)d_in[0];   // (65536, 512)
    const float* km = (const float*)d_in[1];   // (1024, 512)
    const float* vm = (const float*)d_in[2];   // (1024, 1024)
    float* out = (float*)d_out;                // (65536, 1024)

    void *p_qn = nullptr, *p_kn = nullptr, *p_valT = nullptr, *p_sharp = nullptr;
    cudaGetSymbolAddress(&p_qn, g_qn);
    cudaGetSymbolAddress(&p_kn, g_kn);
    cudaGetSymbolAddress(&p_valT, g_valT);
    cudaGetSymbolAddress(&p_sharp, g_sharp);

    cudaFuncSetAttribute(gemm_kernel<512, 0>,
                         cudaFuncAttributeMaxDynamicSharedMemorySize, SMEM_TOTAL);
    cudaFuncSetAttribute(gemm_kernel<1024, 1>,
                         cudaFuncAttributeMaxDynamicSharedMemorySize, SMEM_TOTAL);

    // 1) normalize keys -> fp16
    prep_norm_kernel<<<C_DIM / 8, 256>>>(km, (__half*)p_kn);
    // 2) transpose + convert val_mem -> fp16
    transpose_val_kernel<<<dim3(32, 32), 256>>>(vm);
    // 3) normalize queries -> fp16
    prep_norm_kernel<<<B_ROWS / 8, 256>>>(q, (__half*)p_qn);
    // 4) sim GEMM + softabs -> g_sharp      grid: (8 N-tiles, 256 M-tiles)
    gemm_kernel<512, 0><<<dim3(C_DIM / NT, B_ROWS / MT), 256, SMEM_TOTAL>>>(
        (const __half*)p_qn, (const __half*)p_kn, nullptr);
    // 5) deterministic row sums of sharp -> g_rowinv
    rowsum_kernel<<<B_ROWS / 8, 256>>>();
    // 6) value GEMM + normalize -> out
    gemm_kernel<1024, 1><<<dim3(C_DIM / NT, B_ROWS / MT), 256, SMEM_TOTAL>>>(
        (const __half*)p_sharp, (const __half*)p_valT, out);
}

// round 7
// speedup vs baseline: 1.2802x; 1.2802x over previous
#include <cuda_runtime.h>
#include <cuda_fp16.h>
#include <cstdint>

// ============================ constants ============================

static constexpr int B_ROWS = 65536;   // query rows
static constexpr int D_DIM  = 512;     // feature dim
static constexpr int C_DIM  = 1024;    // memory slots

static constexpr int MT = 128;         // CTA tile M
static constexpr int NT = 128;         // CTA tile N
static constexpr int KC = 64;          // K per smem stage (64 halves = 128B rows)

static constexpr uint32_t A_STAGE = MT * 128;              // 16384
static constexpr uint32_t B_STAGE = NT * 128;              // 16384
static constexpr uint32_t STAGE_BYTES = A_STAGE + B_STAGE; // 32768
static constexpr uint32_t SMEM_TOTAL  = 3 * STAGE_BYTES;   // 98304

// ============================ device scratch ============================

__device__ __align__(1024) __half g_qn[(size_t)B_ROWS * D_DIM];     // 64 MB
__device__ __align__(1024) __half g_kn[(size_t)C_DIM * D_DIM];      // 1 MB
__device__ __align__(1024) __half g_valT[(size_t)C_DIM * C_DIM];    // 2 MB
__device__ __align__(1024) __half g_sharp[(size_t)B_ROWS * C_DIM];  // 128 MB
__device__ float g_rowinv[B_ROWS];

// ============================ helpers ============================

__device__ __forceinline__ uint32_t smem_to_u32(const void* smem_ptr) {
    uint32_t addr;
    asm("{ .reg .u64 tmp; cvta.to.shared.u64 tmp, %1; cvt.u32.u64 %0, tmp; }"
        : "=r"(addr) : "l"(smem_ptr));
    return addr;
}

__device__ __forceinline__ void cp_async16(uint32_t dst, const void* src) {
    asm volatile("cp.async.cg.shared.global [%0], [%1], 16;"
                 :: "r"(dst), "l"(src) : "memory");
}

__device__ __forceinline__ void ldmatrix_x4(uint32_t* r, uint32_t addr) {
    asm volatile("ldmatrix.sync.aligned.m8n8.x4.shared.b16 {%0,%1,%2,%3}, [%4];"
                 : "=r"(r[0]), "=r"(r[1]), "=r"(r[2]), "=r"(r[3]) : "r"(addr));
}

__device__ __forceinline__ void mma16816(float* c, const uint32_t* a,
                                         uint32_t b0, uint32_t b1) {
    asm volatile(
        "mma.sync.aligned.m16n8k16.row.col.f32.f16.f16.f32 "
        "{%0,%1,%2,%3}, {%4,%5,%6,%7}, {%8,%9}, {%0,%1,%2,%3};"
        : "+f"(c[0]), "+f"(c[1]), "+f"(c[2]), "+f"(c[3])
        : "r"(a[0]), "r"(a[1]), "r"(a[2]), "r"(a[3]), "r"(b0), "r"(b1));
}

__device__ __forceinline__ float softabs_f(float x) {
    const float t = 10.f * x;
    const float a = 1.f / (1.f + __expf(5.f - t));
    const float b = 1.f / (1.f + __expf(5.f + t));
    return a + b;
}

// swizzled smem byte offset (used only for cp.async dst precompute)
__device__ __forceinline__ uint32_t swz_off(int row, int kchunk) {
    return (uint32_t)(row * 128 + ((kchunk ^ (row & 7)) << 4));
}

// ============================ prep kernels ============================

__global__ void __launch_bounds__(256) prep_norm_kernel(
    const float* __restrict__ src, __half* __restrict__ dst)
{
    const int wid  = threadIdx.x >> 5;
    const int lane = threadIdx.x & 31;
    const size_t row = (size_t)blockIdx.x * 8 + wid;

    const float4* s4 = (const float4*)(src + row * D_DIM);
    float4 v[4];
    float ss = 0.f;
#pragma unroll
    for (int i = 0; i < 4; i++) {
        v[i] = s4[lane + 32 * i];
        ss += v[i].x * v[i].x + v[i].y * v[i].y + v[i].z * v[i].z + v[i].w * v[i].w;
    }
#pragma unroll
    for (int o = 16; o > 0; o >>= 1) ss += __shfl_xor_sync(0xffffffffu, ss, o);
    const float inv = rsqrtf(ss + 1e-12f);

    uint2* d2 = (uint2*)(dst + row * D_DIM);
#pragma unroll
    for (int i = 0; i < 4; i++) {
        __half2 a = __floats2half2_rn(v[i].x * inv, v[i].y * inv);
        __half2 b = __floats2half2_rn(v[i].z * inv, v[i].w * inv);
        d2[lane + 32 * i] = make_uint2(*reinterpret_cast<uint32_t*>(&a),
                                       *reinterpret_cast<uint32_t*>(&b));
    }
}

__global__ void __launch_bounds__(256) transpose_val_kernel(const float* __restrict__ v)
{
    __shared__ float t[32][33];
    const int tx = threadIdx.x & 31;
    const int ty = threadIdx.x >> 5;
    const int x  = blockIdx.x * 32 + tx;
    const int y0 = blockIdx.y * 32 + ty;
#pragma unroll
    for (int i = 0; i < 4; i++)
        t[ty + i * 8][tx] = v[(size_t)(y0 + i * 8) * C_DIM + x];
    __syncthreads();
    const int x2 = blockIdx.y * 32 + tx;
    const int y2 = blockIdx.x * 32 + ty;
#pragma unroll
    for (int i = 0; i < 4; i++)
        g_valT[(size_t)(y2 + i * 8) * C_DIM + x2] = __float2half(t[tx][ty + i * 8]);
}

// Deterministic per-row sum of g_sharp -> g_rowinv = 1/sum. One warp per row.
__global__ void __launch_bounds__(256) rowsum_kernel()
{
    const int wid  = threadIdx.x >> 5;
    const int lane = threadIdx.x & 31;
    const size_t row = (size_t)blockIdx.x * 8 + wid;

    const uint4* s4 = (const uint4*)(g_sharp + row * C_DIM);
    float ss = 0.f;
#pragma unroll
    for (int i = 0; i < 4; i++) {
        uint4 v = s4[lane + 32 * i];
        const __half2* h2 = (const __half2*)&v;
#pragma unroll
        for (int q = 0; q < 4; q++) {
            float2 f = __half22float2(h2[q]);
            ss += f.x + f.y;
        }
    }
#pragma unroll
    for (int o = 16; o > 0; o >>= 1) ss += __shfl_xor_sync(0xffffffffu, ss, o);
    if (lane == 0) g_rowinv[row] = 1.0f / ss;
}

// ============================ GEMM ============================
// D[m][n] = sum_k A[m][k]*B[n][k]; fp16 in, fp32 accum (mma.sync m16n8k16).
// CTA tile 128x128, 8 warps (2x4), warp tile 64x32, 3-stage cp.async ring,
// one __syncthreads per K-chunk, 2 CTAs/SM.
// EPI==0: store softabs(acc) -> g_sharp (fp16)
// EPI==1: store acc * g_rowinv[row] -> out (fp32)
template<int KTOT, int EPI>
__global__ void __launch_bounds__(256, 2)
gemm_kernel(const __half* __restrict__ A, const __half* __restrict__ B,
            float* __restrict__ out)
{
    extern __shared__ char smem[];
    const uint32_t sbase = smem_to_u32(smem);
    const int tid  = threadIdx.x;
    const int lane = tid & 31;
    const int wid  = tid >> 5;
    const int warp_m = wid >> 2;      // 0..1  (64 rows each)
    const int warp_n = wid & 3;       // 0..3  (32 cols each)
    const int mbase = blockIdx.y * MT;
    const int nbase = blockIdx.x * NT;

    constexpr int NCH = KTOT / KC;

    float acc[4][4][4];
#pragma unroll
    for (int a = 0; a < 4; a++)
#pragma unroll
        for (int b = 0; b < 4; b++)
#pragma unroll
            for (int c = 0; c < 4; c++) acc[a][b][c] = 0.f;

    // ---- precomputed ldmatrix base addresses (stage 0) ----
    // chunk index for this lane at k-step ks: (2*ks + c0) ^ (row & 7)
    //  = basechunk(bit4) ^ (2*ks<<4) ^ r6s   (bits 5..6 disjoint from bit 4)
    const int lrow15 = lane & 15;
    const int c0  = lane >> 4;
    const int r7  = lrow15 & 7;
    const uint32_t basechunk = (uint32_t)((c0 ^ (r7 & 1)) << 4);
    const uint32_t r6s = (uint32_t)((r7 & 6) << 4);

    uint32_t aAddr0[4], bAddr0[2];
#pragma unroll
    for (int mt = 0; mt < 4; mt++) {
        const int row = warp_m * 64 + mt * 16 + lrow15;
        aAddr0[mt] = sbase + (uint32_t)(row << 7) + basechunk;
    }
#pragma unroll
    for (int p = 0; p < 2; p++) {
        const int row = warp_n * 32 + p * 16 + lrow15;
        bAddr0[p] = sbase + A_STAGE + (uint32_t)(row << 7) + basechunk;
    }

    // ---- precomputed cp.async src/dst bases ----
    const int r0  = tid >> 3;              // rows: r0 + 32*i  (i=0..3)
    const int cch = tid & 7;               // 16B chunk column
    const char* srcA0 = (const char*)(A + (size_t)(mbase + r0) * KTOT) + cch * 16;
    const char* srcB0 = (const char*)(B + (size_t)(nbase + r0) * KTOT) + cch * 16;
    const uint32_t dstA0 = sbase + swz_off(r0, cch);
    const uint32_t dstB0 = sbase + A_STAGE + swz_off(r0, cch);
    constexpr size_t rowStride = (size_t)32 * KTOT * 2;   // 32 rows in bytes

    auto load_stage = [&](int kc, int s) {
        const uint32_t so = (uint32_t)s * STAGE_BYTES;
        const size_t ko = (size_t)kc * 128;
#pragma unroll
        for (int i = 0; i < 4; i++)
            cp_async16(dstA0 + so + i * 4096u, srcA0 + ko + i * rowStride);
#pragma unroll
        for (int i = 0; i < 4; i++)
            cp_async16(dstB0 + so + i * 4096u, srcB0 + ko + i * rowStride);
        asm volatile("cp.async.commit_group;" ::: "memory");
    };

    auto mma_stage = [&](int s) {
        const uint32_t so = (uint32_t)s * STAGE_BYTES;
#pragma unroll
        for (int ks = 0; ks < 4; ks++) {
            const uint32_t kd = so + (((uint32_t)(ks * 2) << 4) ^ r6s);
            uint32_t bf[2][4];
#pragma unroll
            for (int p = 0; p < 2; p++)
                ldmatrix_x4(bf[p], bAddr0[p] + kd);
#pragma unroll
            for (int mt = 0; mt < 4; mt++) {
                uint32_t af[4];
                ldmatrix_x4(af, aAddr0[mt] + kd);
#pragma unroll
                for (int nt = 0; nt < 4; nt++) {
                    const int p = nt >> 1, lo = nt & 1;
                    mma16816(acc[mt][nt], af, bf[p][lo], bf[p][2 + lo]);
                }
            }
        }
    };

    // ---- 3-stage pipelined main loop, one barrier per K-chunk ----
    load_stage(0, 0);
    load_stage(1, 1);
#pragma unroll 1
    for (int kc = 0; kc < NCH; kc++) {
        if (kc < NCH - 1) asm volatile("cp.async.wait_group 1;" ::: "memory");
        else              asm volatile("cp.async.wait_group 0;" ::: "memory");
        __syncthreads();
        if (kc + 2 < NCH) {
            const int s2 = kc + 2;
            load_stage(s2, s2 - (s2 / 3) * 3);
        }
        mma_stage(kc - (kc / 3) * 3);
    }

    // ---- epilogue (registers + global only) ----
    const int g   = lane >> 2;     // 0..7
    const int tig = lane & 3;      // 0..3
#pragma unroll
    for (int mt = 0; mt < 4; mt++) {
        const int rg = mbase + warp_m * 64 + mt * 16 + g;
        if (EPI == 0) {
#pragma unroll
            for (int nt = 0; nt < 4; nt++) {
                const int n = nbase + warp_n * 32 + nt * 8 + tig * 2;
                __half2 h0 = __floats2half2_rn(softabs_f(acc[mt][nt][0]),
                                               softabs_f(acc[mt][nt][1]));
                __half2 h1 = __floats2half2_rn(softabs_f(acc[mt][nt][2]),
                                               softabs_f(acc[mt][nt][3]));
                *(__half2*)(g_sharp + (size_t)rg * C_DIM + n) = h0;
                *(__half2*)(g_sharp + (size_t)(rg + 8) * C_DIM + n) = h1;
            }
        } else {
            const float i0 = g_rowinv[rg];
            const float i1 = g_rowinv[rg + 8];
#pragma unroll
            for (int nt = 0; nt < 4; nt++) {
                const int n = nbase + warp_n * 32 + nt * 8 + tig * 2;
                *(float2*)(out + (size_t)rg * C_DIM + n) =
                    make_float2(acc[mt][nt][0] * i0, acc[mt][nt][1] * i0);
                *(float2*)(out + (size_t)(rg + 8) * C_DIM + n) =
                    make_float2(acc[mt][nt][2] * i1, acc[mt][nt][3] * i1);
            }
        }
    }
}

// ============================ launcher ============================

extern "C" void kernel_launch(void* const* d_in, const int* in_sizes, int n_in,
                              void* d_out, int out_size)
{
    const float* q  = (const float*)d_in[0];   // (65536, 512)
    const float* km = (const float*)d_in[1];   // (1024, 512)
    const float* vm = (const float*)d_in[2];   // (1024, 1024)
    float* out = (float*)d_out;                // (65536, 1024)

    void *p_qn = nullptr, *p_kn = nullptr, *p_valT = nullptr, *p_sharp = nullptr;
    cudaGetSymbolAddress(&p_qn, g_qn);
    cudaGetSymbolAddress(&p_kn, g_kn);
    cudaGetSymbolAddress(&p_valT, g_valT);
    cudaGetSymbolAddress(&p_sharp, g_sharp);

    cudaFuncSetAttribute(gemm_kernel<512, 0>,
                         cudaFuncAttributeMaxDynamicSharedMemorySize, SMEM_TOTAL);
    cudaFuncSetAttribute(gemm_kernel<1024, 1>,
                         cudaFuncAttributeMaxDynamicSharedMemorySize, SMEM_TOTAL);

    // 1) normalize keys -> fp16
    prep_norm_kernel<<<C_DIM / 8, 256>>>(km, (__half*)p_kn);
    // 2) transpose + convert val_mem -> fp16
    transpose_val_kernel<<<dim3(32, 32), 256>>>(vm);
    // 3) normalize queries -> fp16
    prep_norm_kernel<<<B_ROWS / 8, 256>>>(q, (__half*)p_qn);
    // 4) sim GEMM + softabs -> g_sharp      grid: (8 N-tiles, 512 M-tiles)
    gemm_kernel<512, 0><<<dim3(C_DIM / NT, B_ROWS / MT), 256, SMEM_TOTAL>>>(
        (const __half*)p_qn, (const __half*)p_kn, nullptr);
    // 5) deterministic row sums of sharp -> g_rowinv
    rowsum_kernel<<<B_ROWS / 8, 256>>>();
    // 6) value GEMM + normalize -> out
    gemm_kernel<1024, 1><<<dim3(C_DIM / NT, B_ROWS / MT), 256, SMEM_TOTAL>>>(
        (const __half*)p_sharp, (const __half*)p_valT, out);
}